// round 10
// baseline (speedup 1.0000x reference)
#include <cuda_runtime.h>
#include <cstddef>

// DPLoss: mean over B rows of [ sum_{j<len[i]} (pred[i,j]-log(align[i,j]))^2 / len[i] ]
// B=4096, T=2048, fp32, len ~ U[1,2048].
//
// R10: prefix-only loads (~34MB, locked in since R8) + warp-level dynamic
// ticket scheduling over half-row units (8192). Persistent warps keep the
// SM full until the queue drains (fixes R9's retirement tail); the next
// ticket is prefetched so the atomic's 318cyc latency hides under the
// current unit. No __syncthreads anywhere. Unit body = R9's front-batched
// predicated LDG.128 groups (MLP~8/lane). Last-warp-out finalization with
// self-reset (CUDA-graph replay safe).

#define B_ROWS   4096
#define T_VEC4   512                    // float4 per full row
#define UNITS    (B_ROWS * 2)           // half-row units
#define HALF_V4  256                    // vec4 per half row
#define NTHREADS 128
#define NCTAS    1024
#define NWARPS   (NCTAS * (NTHREADS / 32))   // 4096

__device__ float    g_acc    = 0.0f;
__device__ unsigned g_count  = 0;
__device__ unsigned g_ticket = 0;

__global__ __launch_bounds__(NTHREADS) void dploss_kernel(
    const float4* __restrict__ pred,
    const float4* __restrict__ align,
    const int* __restrict__ lens,
    float* __restrict__ out)
{
    const int lane = threadIdx.x & 31;

    float acc = 0.0f;

    // initial ticket
    unsigned t = 0;
    if (lane == 0) t = atomicAdd(&g_ticket, 1u);
    t = __shfl_sync(0xFFFFFFFFu, t, 0);

    while (t < UNITS) {
        // prefetch next ticket; result consumed only after this unit's work
        unsigned tn = 0;
        if (lane == 0) tn = atomicAdd(&g_ticket, 1u);

        const int row  = t >> 1;
        const int half = t & 1;
        const int len  = __ldg(lens + row);
        const int nvec = (len + 3) >> 2;
        const int base = half << 8;                  // 0 or 256
        const int cnt  = nvec - base;                // vec4s in this half (may be <=0)

        if (cnt > 0) {
            const float4* __restrict__ p = pred  + (size_t)row * T_VEC4 + base;
            const float4* __restrict__ a = align + (size_t)row * T_VEC4 + base;
            const int lim = (cnt < HALF_V4) ? cnt : HALF_V4;

            float rs = 0.0f;
            #pragma unroll
            for (int g = 0; g < HALF_V4; g += 128) {     // 2 groups of 4 vec4/lane
                if (g < lim) {
                    float4 pv[4], av[4];
                    bool   ok[4];
                    #pragma unroll
                    for (int m = 0; m < 4; ++m) {
                        const int i = g + m * 32 + lane;
                        ok[m] = (i < lim);
                        if (ok[m]) { pv[m] = p[i]; av[m] = a[i]; }
                    }
                    #pragma unroll
                    for (int m = 0; m < 4; ++m) {
                        if (ok[m]) {
                            const int j = (base + g + m * 32 + lane) << 2;
                            float d0 = pv[m].x - __logf(av[m].x);
                            float d1 = pv[m].y - __logf(av[m].y);
                            float d2 = pv[m].z - __logf(av[m].z);
                            float d3 = pv[m].w - __logf(av[m].w);
                            if (j + 4 <= len) {
                                rs += d0 * d0 + d1 * d1 + d2 * d2 + d3 * d3;
                            } else {
                                rs += d0 * d0;
                                if (j + 1 < len) rs += d1 * d1;
                                if (j + 2 < len) rs += d2 * d2;
                                if (j + 3 < len) rs += d3 * d3;
                            }
                        }
                    }
                }
            }
            acc += rs * __fdividef(1.0f, (float)len);
        }

        t = __shfl_sync(0xFFFFFFFFu, tn, 0);
    }

    // warp reduction
    #pragma unroll
    for (int off = 16; off > 0; off >>= 1)
        acc += __shfl_down_sync(0xFFFFFFFFu, acc, off);

    if (lane == 0) {
        atomicAdd(&g_acc, acc);
        __threadfence();
        unsigned prev = atomicInc(&g_count, NWARPS - 1);
        if (prev == NWARPS - 1) {
            // all warps done: their final (over-limit) ticket grabs happened
            // before their count arrive, so resetting now is race-free.
            float total = atomicExch(&g_acc, 0.0f);
            g_ticket = 0;
            *out = total * (1.0f / (float)B_ROWS);
        }
    }
}

extern "C" void kernel_launch(void* const* d_in, const int* in_sizes, int n_in,
                              void* d_out, int out_size)
{
    const float4* pred  = (const float4*)d_in[0];
    const float4* align = (const float4*)d_in[1];
    const int*    lens  = (const int*)d_in[2];
    float* out = (float*)d_out;

    dploss_kernel<<<NCTAS, NTHREADS>>>(pred, align, lens, out);
}

// round 11
// speedup vs baseline: 1.9587x; 1.9587x over previous
#include <cuda_runtime.h>
#include <cstddef>

// DPLoss: mean over B rows of [ sum_{j<len[i]} (pred[i,j]-log(align[i,j]))^2 / len[i] ]
// B=4096, T=2048, fp32, len ~ U[1,2048].
//
// R11 = R4's measured-best structure (flat grid-stride over half-row units,
// 1184-CTA single wave, wall 12.7us) with dead work removed:
//   - whole-unit skip when the unit lies entirely beyond len (~25% of units)
//   - per-thread skip when this thread's vec4 lies beyond len
//   -> ~36MB effective traffic instead of 67MB, identical schedule otherwise.
// Timed regime is warm-L2 (inputs fit in 126MB L2), so bytes cut there pay
// off directly if bandwidth-bound; if the 12.7us cluster is a floor, this is
// neutral and diagnostic.

#define B_ROWS   4096
#define T_COLS   2048
#define T_VEC4   (T_COLS / 4)         // 512 float4 per row
#define NTHREADS 256
#define NCTAS    1184                 // 148 SMs * 8 CTA/SM -> single wave
#define UNITS    (B_ROWS * 2)         // half-row units

__device__ float    g_acc   = 0.0f;
__device__ unsigned g_count = 0;

__global__ __launch_bounds__(NTHREADS, 8) void dploss_kernel(
    const float4* __restrict__ pred,
    const float4* __restrict__ align,
    const int* __restrict__ lens,
    float* __restrict__ out)
{
    float s = 0.0f;

    for (int u = blockIdx.x; u < UNITS; u += NCTAS) {
        const int row   = u >> 1;
        const int len   = __ldg(lens + row);          // 16KB, L1-resident
        const int jbase = (u & 1) << 10;              // 0 or 1024
        if (jbase >= len) continue;                   // unit fully masked

        const int i = ((u & 1) << 8) | threadIdx.x;   // vec4 index in row
        const int j = i << 2;                         // element index in row
        if (j >= len) continue;                       // this thread's vec4 masked

        const size_t base = (size_t)row * T_VEC4 + i;
        float4 pv = pred[base];
        float4 av = align[base];

        float d0 = pv.x - __logf(av.x);
        float d1 = pv.y - __logf(av.y);
        float d2 = pv.z - __logf(av.z);
        float d3 = pv.w - __logf(av.w);

        float rs;
        if (j + 4 <= len) {                           // fully valid (common)
            rs = d0 * d0 + d1 * d1 + d2 * d2 + d3 * d3;
        } else {                                      // row's last vec4
            rs = d0 * d0;
            if (j + 1 < len) rs += d1 * d1;
            if (j + 2 < len) rs += d2 * d2;
            if (j + 3 < len) rs += d3 * d3;
        }

        s += rs * __fdividef(1.0f, (float)len);
    }

    // warp reduction
    #pragma unroll
    for (int off = 16; off > 0; off >>= 1)
        s += __shfl_down_sync(0xFFFFFFFFu, s, off);

    // block reduction across 8 warps
    __shared__ float warp_sums[NTHREADS / 32];
    const int wid = threadIdx.x >> 5;
    const int lid = threadIdx.x & 31;
    if (lid == 0) warp_sums[wid] = s;
    __syncthreads();

    if (wid == 0) {
        float v = (lid < NTHREADS / 32) ? warp_sums[lid] : 0.0f;
        #pragma unroll
        for (int off = 4; off > 0; off >>= 1)
            v += __shfl_down_sync(0xFFFFFFFFu, v, off);

        if (lid == 0) {
            atomicAdd(&g_acc, v);
            __threadfence();
            unsigned prev = atomicInc(&g_count, NCTAS - 1);
            if (prev == NCTAS - 1) {
                float total = atomicExch(&g_acc, 0.0f);   // read + reset for replay
                *out = total * (1.0f / (float)B_ROWS);
            }
        }
    }
}

extern "C" void kernel_launch(void* const* d_in, const int* in_sizes, int n_in,
                              void* d_out, int out_size)
{
    const float4* pred  = (const float4*)d_in[0];
    const float4* align = (const float4*)d_in[1];
    const int*    lens  = (const int*)d_in[2];
    float* out = (float*)d_out;

    dploss_kernel<<<NCTAS, NTHREADS>>>(pred, align, lens, out);
}